// round 14
// baseline (speedup 1.0000x reference)
#include <cuda_runtime.h>
#include <cuda_fp16.h>
#include <mma.h>
#include <math.h>

using namespace nvcuda;

#define NNODES 100000
#define NEDGES 1600000
#define DH     128
#define DOUT   40
#define BNEPS  1e-5f
#define NPAD   (NNODES + 128)   // padding rows so full-tile stores never escape the buffer

// -------------------- scratch (static device globals) -----------------------
__device__ __align__(16) __half g_h[(size_t)NPAD * DH];    // h' = dinv[row]*(act(A)@W), fp16 gather operand
__device__ __align__(16) __half g_a[(size_t)NPAD * DH];    // activations (fp16, raw pre-BN)
__device__ __align__(16) __half g_w1h[DH * DH];            // W1 fp16
__device__ __align__(16) __half g_w2h[DH * DH];            // W2 fp16
__device__ __align__(16) __half g_wfh[DH * 64];            // Wf fp16, padded 40->64 cols
__device__ __align__(16) __half g_bnh[256];                // [0:128) half scale, [128:256) half shift
__device__ __align__(16) float  g_dinv[NNODES];            // rsqrt(deg+1)
__device__ __align__(16) int    g_cnt[NNODES];             // in-degree
__device__ __align__(16) int    g_off[NNODES];             // CSR range begin (unordered ranges)
__device__ __align__(16) int    g_end[NNODES];             // CSR range end
__device__ __align__(16) int    g_cur[NNODES];             // scatter cursors
__device__ __align__(16) int    g_csr[NEDGES];             // src ids grouped by dst
__device__ __align__(16) float  g_bn[512];                 // [0:128) sum, [128:256) sumsq, [256:384) scale, [384:512) shift
__device__ int g_total;                                    // atomic base for range allocation
__device__ int g_is64;

// ------------- init: dtype detect + zero cnt + zero BN sums + total ----------
__global__ void k_init(const long long* __restrict__ ei) {
    int b = blockIdx.x, t = threadIdx.x;
    if (b == 0) {
        __shared__ int sbad[8];
        long long stride = NEDGES / 256;
        long long v = ei[(long long)t * stride];
        bool bad = ((unsigned long long)v >= (unsigned long long)NNODES);
        unsigned anybad = __ballot_sync(0xffffffffu, bad);
        int w = t >> 5;
        if ((t & 31) == 0) sbad[w] = (anybad != 0);
        __syncthreads();
        if (t == 0) {
            int any = 0;
            #pragma unroll
            for (int i = 0; i < 8; i++) any |= sbad[i];
            g_is64 = any ? 0 : 1;
            g_total = 0;
        }
        g_bn[t] = 0.f;   // zero layer sums [0,256)
    } else {
        // blocks 1..64 zero g_cnt (25000 int4)
        int4 z = make_int4(0, 0, 0, 0);
        for (int i = (b - 1) * 256 + t; i < NNODES / 4; i += 64 * 256)
            ((int4*)g_cnt)[i] = z;
    }
}

// -------------------- W fp32 -> fp16 precompute (W1, W2, Wf-padded) ----------
__global__ void k_wconv(const float* __restrict__ W1, const float* __restrict__ W2,
                        const float* __restrict__ Wf) {
    int i = blockIdx.x * 256 + threadIdx.x;   // 64 blocks x 256 = 16384
    g_w1h[i] = __float2half(W1[i]);
    g_w2h[i] = __float2half(W2[i]);
    if (i < DH * 64) {
        int col = i & 63;
        g_wfh[i] = (col < DOUT) ? __float2half(Wf[(i >> 6) * DOUT + col]) : __float2half(0.f);
    }
}

// -------------------- degree (2 edges per thread, vector loads) --------------
__global__ void k_degree(const void* __restrict__ ei) {
    int t = blockIdx.x * blockDim.x + threadIdx.x;
    int e = t * 2;
    if (e >= NEDGES) return;
    int d0, d1;
    if (g_is64) {
        longlong2 p = *(const longlong2*)((const long long*)ei + NEDGES + e);
        d0 = (int)p.x; d1 = (int)p.y;
    } else {
        int2 p = *(const int2*)((const int*)ei + NEDGES + e);
        d0 = p.x; d1 = p.y;
    }
    atomicAdd(&g_cnt[d0], 1);
    atomicAdd(&g_cnt[d1], 1);
}

// ----- one-kernel range allocation: block scan + atomic base (+ dinv) --------
// Ranges are disjoint but NOT node-ordered — agg uses g_off/g_end pairs.
__global__ void k_scanA() {
    __shared__ int sh[1024];
    __shared__ int base;
    int t = threadIdx.x;
    int i = blockIdx.x * 1024 + t;
    int v = (i < NNODES) ? g_cnt[i] : 0;
    sh[t] = v;
    __syncthreads();
    for (int off = 1; off < 1024; off <<= 1) {
        int x = (t >= off) ? sh[t - off] : 0;
        __syncthreads();
        sh[t] += x;
        __syncthreads();
    }
    if (t == 1023) base = atomicAdd(&g_total, sh[1023]);
    __syncthreads();
    if (i < NNODES) {
        int o = base + sh[t] - v;   // exclusive within block + block base
        g_off[i] = o;
        g_cur[i] = o;
        g_end[i] = o + v;
        g_dinv[i] = rsqrtf((float)v + 1.0f);
    }
}

// -------------------- scatter edges into CSR (2 edges per thread) ------------
__global__ void k_scatter(const void* __restrict__ ei) {
    int t = blockIdx.x * blockDim.x + threadIdx.x;
    int e = t * 2;
    if (e >= NEDGES) return;
    int s0, d0, s1, d1;
    if (g_is64) {
        const long long* p = (const long long*)ei;
        longlong2 sp = *(const longlong2*)(p + e);
        longlong2 dp = *(const longlong2*)(p + NEDGES + e);
        s0 = (int)sp.x; s1 = (int)sp.y; d0 = (int)dp.x; d1 = (int)dp.y;
    } else {
        const int* p = (const int*)ei;
        int2 sp = *(const int2*)(p + e);
        int2 dp = *(const int2*)(p + NEDGES + e);
        s0 = sp.x; s1 = sp.y; d0 = dp.x; d1 = dp.y;
    }
    g_csr[atomicAdd(&g_cur[d0], 1)] = s0;
    g_csr[atomicAdd(&g_cur[d1], 1)] = s1;
}

// -------------------- fp16 HMMA GEMM  C[M,128] = dinv[row]*(act(A)@W) --------
// Block: 128x128 tile, 8 warps as 4(M) x 2(N); warp 32x64 = 2x4 m16n16k16 tiles.
template <bool A_HALF, bool APPLY_BN>
__global__ void __launch_bounds__(256)
k_gemm128_h(const void* __restrict__ Av, const __half* __restrict__ Wh,
            __half* __restrict__ C, int M) {
    __shared__ __half As[128][40];    // 128 rows x 32 k (pad 8 halves)
    __shared__ __half Bs[32][136];    // 32 k x 128 n   (pad 8)

    const int tid   = threadIdx.x;
    const int warp  = tid >> 5;
    const int lane  = tid & 31;
    const int warpM = warp >> 1;     // 0..3
    const int warpN = warp & 1;      // 0..1
    const int blockRow = blockIdx.x * 128;

    wmma::fragment<wmma::accumulator, 16, 16, 16, float> acc[2][4];
    #pragma unroll
    for (int i = 0; i < 2; i++)
        #pragma unroll
        for (int j = 0; j < 4; j++)
            wmma::fill_fragment(acc[i][j], 0.0f);

    for (int kt = 0; kt < 4; kt++) {
        #pragma unroll
        for (int it = 0; it < 4; it++) {
            int idx = tid + it * 256;            // 0..1023
            int r   = idx >> 3;                  // 0..127
            int c4  = idx & 7;                   // 4-half group
            int grow = blockRow + r;
            uint2 packed;
            if (A_HALF) {
                uint2 raw = *(const uint2*)((const __half*)Av + (size_t)grow * 128 + kt * 32 + c4 * 4);
                if (APPLY_BN) {
                    int c = kt * 32 + c4 * 4;
                    __half2 sc0 = *(const __half2*)&g_bnh[c];
                    __half2 sc1 = *(const __half2*)&g_bnh[c + 2];
                    __half2 sh0 = *(const __half2*)&g_bnh[128 + c];
                    __half2 sh1 = *(const __half2*)&g_bnh[128 + c + 2];
                    __half2 z = __float2half2_rn(0.f);
                    __half2 v0 = __hmax2(__hfma2(*(__half2*)&raw.x, sc0, sh0), z);
                    __half2 v1 = __hmax2(__hfma2(*(__half2*)&raw.y, sc1, sh1), z);
                    packed.x = *(unsigned*)&v0; packed.y = *(unsigned*)&v1;
                } else {
                    packed = raw;
                }
            } else {
                float4 v = make_float4(0.f, 0.f, 0.f, 0.f);
                if (grow < M) v = *(const float4*)((const float*)Av + (size_t)grow * 128 + kt * 32 + c4 * 4);
                __half2 h0 = __floats2half2_rn(v.x, v.y);
                __half2 h1 = __floats2half2_rn(v.z, v.w);
                packed.x = *(unsigned*)&h0; packed.y = *(unsigned*)&h1;
            }
            *(uint2*)&As[r][c4 * 4] = packed;
        }
        #pragma unroll
        for (int it = 0; it < 4; it++) {
            int idx = tid + it * 256;
            int r   = idx >> 5;                  // 0..31
            int c4  = idx & 31;
            *(uint2*)&Bs[r][c4 * 4] = *(const uint2*)(Wh + (size_t)(kt * 32 + r) * 128 + c4 * 4);
        }
        __syncthreads();

        #pragma unroll
        for (int ks = 0; ks < 2; ks++) {
            wmma::fragment<wmma::matrix_a, 16, 16, 16, __half, wmma::row_major> af[2];
            wmma::fragment<wmma::matrix_b, 16, 16, 16, __half, wmma::row_major> bfr[4];
            #pragma unroll
            for (int i = 0; i < 2; i++)
                wmma::load_matrix_sync(af[i], &As[warpM * 32 + i * 16][ks * 16], 40);
            #pragma unroll
            for (int j = 0; j < 4; j++)
                wmma::load_matrix_sync(bfr[j], &Bs[ks * 16][warpN * 64 + j * 16], 136);
            #pragma unroll
            for (int i = 0; i < 2; i++)
                #pragma unroll
                for (int j = 0; j < 4; j++)
                    wmma::mma_sync(acc[i][j], af[i], bfr[j], acc[i][j]);
        }
        __syncthreads();
    }

    const int gid = lane >> 2;     // 0..7
    const int tig = lane & 3;      // 0..3
    #pragma unroll
    for (int i = 0; i < 2; i++) {
        int r0 = blockRow + warpM * 32 + i * 16 + gid;
        int r1 = r0 + 8;
        float d0 = (r0 < M) ? g_dinv[r0] : 0.f;
        float d1 = (r1 < M) ? g_dinv[r1] : 0.f;
        #pragma unroll
        for (int j = 0; j < 4; j++) {
            int c0 = warpN * 64 + j * 16 + tig * 2;
            __half2 p00 = __floats2half2_rn(acc[i][j].x[0] * d0, acc[i][j].x[1] * d0);
            __half2 p10 = __floats2half2_rn(acc[i][j].x[2] * d1, acc[i][j].x[3] * d1);
            __half2 p01 = __floats2half2_rn(acc[i][j].x[4] * d0, acc[i][j].x[5] * d0);
            __half2 p11 = __floats2half2_rn(acc[i][j].x[6] * d1, acc[i][j].x[7] * d1);
            *(__half2*)(C + (size_t)r0 * 128 + c0)     = p00;
            *(__half2*)(C + (size_t)r1 * 128 + c0)     = p10;
            *(__half2*)(C + (size_t)r0 * 128 + c0 + 8) = p01;
            *(__half2*)(C + (size_t)r1 * 128 + c0 + 8) = p11;
        }
    }
}

// ---------- fp16 HMMA GEMM  C[M,40] = dinv[row]*(relu(bn(A))@Wf) -------------
__global__ void __launch_bounds__(256)
k_gemm40_h(const __half* __restrict__ A, const __half* __restrict__ Wh,
           __half* __restrict__ C, int M) {
    __shared__ __half As[128][40];    // 128 rows x 32 k
    __shared__ __half Bs[32][72];     // 32 k x 64 n (pad 8)

    const int tid   = threadIdx.x;
    const int warp  = tid >> 5;
    const int lane  = tid & 31;
    const int warpM = warp >> 1;     // 0..3
    const int warpN = warp & 1;      // 0..1
    const int blockRow = blockIdx.x * 128;

    wmma::fragment<wmma::accumulator, 16, 16, 16, float> acc[2][2];
    #pragma unroll
    for (int i = 0; i < 2; i++)
        #pragma unroll
        for (int j = 0; j < 2; j++)
            wmma::fill_fragment(acc[i][j], 0.0f);

    for (int kt = 0; kt < 4; kt++) {
        #pragma unroll
        for (int it = 0; it < 4; it++) {
            int idx = tid + it * 256;
            int r   = idx >> 3;
            int c4  = idx & 7;
            int grow = blockRow + r;
            uint2 raw = *(const uint2*)(A + (size_t)grow * 128 + kt * 32 + c4 * 4);
            int c = kt * 32 + c4 * 4;
            __half2 sc0 = *(const __half2*)&g_bnh[c];
            __half2 sc1 = *(const __half2*)&g_bnh[c + 2];
            __half2 sh0 = *(const __half2*)&g_bnh[128 + c];
            __half2 sh1 = *(const __half2*)&g_bnh[128 + c + 2];
            __half2 z = __float2half2_rn(0.f);
            __half2 v0 = __hmax2(__hfma2(*(__half2*)&raw.x, sc0, sh0), z);
            __half2 v1 = __hmax2(__hfma2(*(__half2*)&raw.y, sc1, sh1), z);
            uint2 packed; packed.x = *(unsigned*)&v0; packed.y = *(unsigned*)&v1;
            *(uint2*)&As[r][c4 * 4] = packed;
        }
        #pragma unroll
        for (int it = 0; it < 2; it++) {
            int idx = tid + it * 256;            // 0..511
            int r   = idx >> 4;                  // 0..31
            int c4  = idx & 15;                  // 0..15
            *(uint2*)&Bs[r][c4 * 4] = *(const uint2*)(Wh + (size_t)(kt * 32 + r) * 64 + c4 * 4);
        }
        __syncthreads();

        #pragma unroll
        for (int ks = 0; ks < 2; ks++) {
            wmma::fragment<wmma::matrix_a, 16, 16, 16, __half, wmma::row_major> af[2];
            wmma::fragment<wmma::matrix_b, 16, 16, 16, __half, wmma::row_major> bfr[2];
            #pragma unroll
            for (int i = 0; i < 2; i++)
                wmma::load_matrix_sync(af[i], &As[warpM * 32 + i * 16][ks * 16], 40);
            #pragma unroll
            for (int j = 0; j < 2; j++)
                wmma::load_matrix_sync(bfr[j], &Bs[ks * 16][warpN * 32 + j * 16], 72);
            #pragma unroll
            for (int i = 0; i < 2; i++)
                #pragma unroll
                for (int j = 0; j < 2; j++)
                    wmma::mma_sync(acc[i][j], af[i], bfr[j], acc[i][j]);
        }
        __syncthreads();
    }

    const int gid = lane >> 2;
    const int tig = lane & 3;
    #pragma unroll
    for (int i = 0; i < 2; i++) {
        int r0 = blockRow + warpM * 32 + i * 16 + gid;
        int r1 = r0 + 8;
        float d0 = (r0 < M) ? g_dinv[r0] : 0.f;
        float d1 = (r1 < M) ? g_dinv[r1] : 0.f;
        #pragma unroll
        for (int j = 0; j < 2; j++) {
            int c0 = warpN * 32 + j * 16 + tig * 2;
            if (c0 < DOUT) {
                __half2 p00 = __floats2half2_rn(acc[i][j].x[0] * d0, acc[i][j].x[1] * d0);
                __half2 p10 = __floats2half2_rn(acc[i][j].x[2] * d1, acc[i][j].x[3] * d1);
                *(__half2*)(C + (size_t)r0 * 40 + c0) = p00;
                *(__half2*)(C + (size_t)r1 * 40 + c0) = p10;
            }
            if (c0 + 8 < DOUT) {
                __half2 p01 = __floats2half2_rn(acc[i][j].x[4] * d0, acc[i][j].x[5] * d0);
                __half2 p11 = __floats2half2_rn(acc[i][j].x[6] * d1, acc[i][j].x[7] * d1);
                *(__half2*)(C + (size_t)r0 * 40 + c0 + 8) = p01;
                *(__half2*)(C + (size_t)r1 * 40 + c0 + 8) = p11;
            }
        }
    }
}

// -------------------- CSR aggregation D=128 (fp16 in/out, pure sum) ----------
__global__ void __launch_bounds__(256)
k_agg128(const __half* __restrict__ h, __half* __restrict__ out,
         const float* __restrict__ bias) {
    __shared__ float ssum[128];
    __shared__ float ssq[128];
    int tid  = threadIdx.x;
    int warp = tid >> 5, lane = tid & 31;
    if (tid < 128) { ssum[tid] = 0.f; ssq[tid] = 0.f; }
    __syncthreads();

    int r = blockIdx.x * 8 + warp;
    bool ok = (r < NNODES);       // warp-uniform
    if (ok) {
        const int co = lane * 4;
        float4 acc;
        {
            uint2 raw = *(const uint2*)(h + (size_t)r * 128 + co);   // self (dinv-scaled)
            float2 f0 = __half22float2(*(__half2*)&raw.x);
            float2 f1 = __half22float2(*(__half2*)&raw.y);
            acc.x = f0.x; acc.y = f0.y; acc.z = f1.x; acc.w = f1.y;
        }
        int base = g_off[r], end = g_end[r];
        for (; base + 8 <= end; base += 8) {
            int idx = 0;
            if (lane < 8) idx = g_csr[base + lane];
            #pragma unroll
            for (int j = 0; j < 8; j++) {
                int s = __shfl_sync(0xffffffffu, idx, j);
                uint2 raw = *(const uint2*)(h + (size_t)s * 128 + co);
                float2 f0 = __half22float2(*(__half2*)&raw.x);
                float2 f1 = __half22float2(*(__half2*)&raw.y);
                acc.x += f0.x; acc.y += f0.y; acc.z += f1.x; acc.w += f1.y;
            }
        }
        int rem = end - base;
        if (rem > 0) {
            int idx = 0;
            if (lane < rem) idx = g_csr[base + lane];
            for (int j = 0; j < rem; j++) {
                int s = __shfl_sync(0xffffffffu, idx, j);
                uint2 raw = *(const uint2*)(h + (size_t)s * 128 + co);
                float2 f0 = __half22float2(*(__half2*)&raw.x);
                float2 f1 = __half22float2(*(__half2*)&raw.y);
                acc.x += f0.x; acc.y += f0.y; acc.z += f1.x; acc.w += f1.y;
            }
        }
        float dr = g_dinv[r];
        float4 b = *(const float4*)(bias + co);
        float4 v;
        v.x = fmaf(acc.x, dr, b.x);
        v.y = fmaf(acc.y, dr, b.y);
        v.z = fmaf(acc.z, dr, b.z);
        v.w = fmaf(acc.w, dr, b.w);
        __half2 h0 = __floats2half2_rn(v.x, v.y);
        __half2 h1 = __floats2half2_rn(v.z, v.w);
        uint2 packed; packed.x = *(unsigned*)&h0; packed.y = *(unsigned*)&h1;
        *(uint2*)(out + (size_t)r * 128 + co) = packed;
        atomicAdd(&ssum[co + 0], v.x);
        atomicAdd(&ssum[co + 1], v.y);
        atomicAdd(&ssum[co + 2], v.z);
        atomicAdd(&ssum[co + 3], v.w);
        atomicAdd(&ssq[co + 0], v.x * v.x);
        atomicAdd(&ssq[co + 1], v.y * v.y);
        atomicAdd(&ssq[co + 2], v.z * v.z);
        atomicAdd(&ssq[co + 3], v.w * v.w);
    }
    __syncthreads();
    if (tid < 128) {
        atomicAdd(&g_bn[tid], ssum[tid]);
        atomicAdd(&g_bn[128 + tid], ssq[tid]);
    }
}

__global__ void k_bnfin(const float* __restrict__ g, const float* __restrict__ be) {
    int c = threadIdx.x;  // 128 threads
    float inv_n = 1.0f / (float)NNODES;
    float mean = g_bn[c] * inv_n;
    float var  = g_bn[128 + c] * inv_n - mean * mean;
    float sc = g[c] * rsqrtf(var + BNEPS);
    float sh = be[c] - mean * sc;
    g_bnh[c]       = __float2half(sc);
    g_bnh[128 + c] = __float2half(sh);
    g_bn[c] = 0.f;           // reset sums for next layer
    g_bn[128 + c] = 0.f;
}

// ------------- CSR aggregation D=40 (fp16 in) + bias + log_softmax -----------
__global__ void __launch_bounds__(256)
k_agg40(const __half* __restrict__ h, float* __restrict__ out,
        const float* __restrict__ bf) {
    int tid  = threadIdx.x;
    int warp = tid >> 5, lane = tid & 31;
    int r = blockIdx.x * 8 + warp;
    if (r >= NNODES) return;     // warp-uniform exit
    bool cok = (lane < 10);

    const int co = lane * 4;
    float4 acc = make_float4(0.f, 0.f, 0.f, 0.f);
    if (cok) {
        uint2 raw = *(const uint2*)(h + (size_t)r * 40 + co);    // self (dinv-scaled)
        float2 f0 = __half22float2(*(__half2*)&raw.x);
        float2 f1 = __half22float2(*(__half2*)&raw.y);
        acc = make_float4(f0.x, f0.y, f1.x, f1.y);
    }
    int base = g_off[r], end = g_end[r];
    for (; base + 8 <= end; base += 8) {
        int idx = 0;
        if (lane < 8) idx = g_csr[base + lane];
        #pragma unroll
        for (int j = 0; j < 8; j++) {
            int s = __shfl_sync(0xffffffffu, idx, j);
            if (cok) {
                uint2 raw = *(const uint2*)(h + (size_t)s * 40 + co);
                float2 f0 = __half22float2(*(__half2*)&raw.x);
                float2 f1 = __half22float2(*(__half2*)&raw.y);
                acc.x += f0.x; acc.y += f0.y; acc.z += f1.x; acc.w += f1.y;
            }
        }
    }
    int rem = end - base;
    if (rem > 0) {
        int idx = 0;
        if (lane < rem) idx = g_csr[base + lane];
        for (int j = 0; j < rem; j++) {
            int s = __shfl_sync(0xffffffffu, idx, j);
            if (cok) {
                uint2 raw = *(const uint2*)(h + (size_t)s * 40 + co);
                float2 f0 = __half22float2(*(__half2*)&raw.x);
                float2 f1 = __half22float2(*(__half2*)&raw.y);
                acc.x += f0.x; acc.y += f0.y; acc.z += f1.x; acc.w += f1.y;
            }
        }
    }
    float dr = g_dinv[r];
    float4 v = make_float4(-1e30f, -1e30f, -1e30f, -1e30f);
    if (cok) {
        float4 b = *(const float4*)(bf + co);
        v.x = fmaf(acc.x, dr, b.x);
        v.y = fmaf(acc.y, dr, b.y);
        v.z = fmaf(acc.z, dr, b.z);
        v.w = fmaf(acc.w, dr, b.w);
    }
    float m = fmaxf(fmaxf(v.x, v.y), fmaxf(v.z, v.w));
    #pragma unroll
    for (int off = 16; off >= 1; off >>= 1)
        m = fmaxf(m, __shfl_xor_sync(0xffffffffu, m, off));
    float s = 0.f;
    if (cok) s = expf(v.x - m) + expf(v.y - m) + expf(v.z - m) + expf(v.w - m);
    #pragma unroll
    for (int off = 16; off >= 1; off >>= 1)
        s += __shfl_xor_sync(0xffffffffu, s, off);
    float l = m + logf(s);
    if (cok) {
        float4 o = make_float4(v.x - l, v.y - l, v.z - l, v.w - l);
        *(float4*)(out + (size_t)r * 40 + co) = o;
    }
}

// ---------------------------------------------------------------------------
extern "C" void kernel_launch(void* const* d_in, const int* in_sizes, int n_in,
                              void* d_out, int out_size) {
    const float* x   = (const float*)d_in[0];
    const void*  ei  = d_in[1];
    const float* W1  = (const float*)d_in[2];
    const float* b1  = (const float*)d_in[3];
    const float* g1  = (const float*)d_in[4];
    const float* be1 = (const float*)d_in[5];
    const float* W2  = (const float*)d_in[6];
    const float* b2  = (const float*)d_in[7];
    const float* g2  = (const float*)d_in[8];
    const float* be2 = (const float*)d_in[9];
    const float* Wf  = (const float*)d_in[10];
    const float* bf  = (const float*)d_in[11];
    float* out = (float*)d_out;

    __half *ph, *pa, *pw1h, *pw2h, *pwfh;
    cudaGetSymbolAddress((void**)&ph, g_h);
    cudaGetSymbolAddress((void**)&pa, g_a);
    cudaGetSymbolAddress((void**)&pw1h, g_w1h);
    cudaGetSymbolAddress((void**)&pw2h, g_w2h);
    cudaGetSymbolAddress((void**)&pwfh, g_wfh);
    __half* ph40 = ph;   // reuse g_h for the fp16 [NPAD,40] final-layer features

    const int M = NNODES;
    const int gemmBlocks = (M + 127) / 128;          // 782
    const int edge2Blocks = (NEDGES / 2 + 255) / 256;// 3125
    const int nodeBlocks = (NNODES + 7) / 8;         // 12500
    const int scanBlocks = (NNODES + 1023) / 1024;   // 98

    static cudaStream_t s2 = [] {
        cudaStream_t s; cudaStreamCreateWithFlags(&s, cudaStreamNonBlocking); return s;
    }();
    static cudaEvent_t eStart = [] {
        cudaEvent_t e; cudaEventCreateWithFlags(&e, cudaEventDisableTiming); return e;
    }();
    static cudaEvent_t eDinv = [] {
        cudaEvent_t e; cudaEventCreateWithFlags(&e, cudaEventDisableTiming); return e;
    }();
    static cudaEvent_t eGemm1 = [] {
        cudaEvent_t e; cudaEventCreateWithFlags(&e, cudaEventDisableTiming); return e;
    }();

    // ---- stream 0: init -> degree -> scanA -> scatter; s2: wconv + gemm1 ----
    k_init<<<65, 256>>>((const long long*)ei);
    cudaEventRecord(eStart, 0);
    cudaStreamWaitEvent(s2, eStart, 0);
    k_wconv<<<64, 256, 0, s2>>>(W1, W2, Wf);

    k_degree<<<edge2Blocks, 256>>>(ei);
    k_scanA<<<scanBlocks, 1024>>>();                 // ranges + cursors + dinv
    cudaEventRecord(eDinv, 0);
    cudaStreamWaitEvent(s2, eDinv, 0);
    k_gemm128_h<false, false><<<gemmBlocks, 256, 0, s2>>>(x, pw1h, ph, M);
    cudaEventRecord(eGemm1, s2);

    k_scatter<<<edge2Blocks, 256>>>(ei);
    cudaStreamWaitEvent(0, eGemm1, 0);

    // ---- layer 1 aggregation onward (serial on stream 0) ----
    k_agg128<<<nodeBlocks, 256>>>(ph, pa, b1);
    k_bnfin<<<1, 128>>>(g1, be1);

    // ---- layer 2 ----
    k_gemm128_h<true, true><<<gemmBlocks, 256>>>(pa, pw2h, ph, M);
    k_agg128<<<nodeBlocks, 256>>>(ph, pa, b2);
    k_bnfin<<<1, 128>>>(g2, be2);

    // ---- layer 3 ----
    k_gemm40_h<<<gemmBlocks, 256>>>(pa, pwfh, ph40, M);
    k_agg40<<<nodeBlocks, 256>>>(ph40, out, bf);
}

// round 15
// speedup vs baseline: 1.2813x; 1.2813x over previous
#include <cuda_runtime.h>
#include <cuda_fp16.h>
#include <mma.h>
#include <math.h>

using namespace nvcuda;

#define NNODES 100000
#define NEDGES 1600000
#define DH     128
#define DOUT   40
#define BNEPS  1e-5f
#define NPAD   (NNODES + 128)   // padding rows so full-tile stores never escape the buffer

// -------------------- scratch (static device globals) -----------------------
__device__ __align__(16) __half g_h[(size_t)NPAD * DH];    // h' = dinv[row]*(act(A)@W), fp16 gather operand
__device__ __align__(16) __half g_a[(size_t)NPAD * DH];    // activations (fp16, raw pre-BN)
__device__ __align__(16) __half g_w1h[DH * DH];            // W1 fp16
__device__ __align__(16) __half g_w2h[DH * DH];            // W2 fp16
__device__ __align__(16) __half g_wfh[DH * 64];            // Wf fp16, padded 40->64 cols
__device__ __align__(16) __half g_bnh[256];                // [0:128) half scale, [128:256) half shift
__device__ __align__(16) float  g_dinv[NNODES];            // rsqrt(deg+1)
__device__ __align__(16) int    g_cnt[NNODES];             // in-degree
__device__ __align__(16) int    g_off[NNODES + 1];         // CSR offsets
__device__ __align__(16) int    g_cur[NNODES];             // scatter cursors
__device__ __align__(16) int    g_csr[NEDGES];             // src ids grouped by dst
__device__ __align__(16) int    g_bsum[128];               // scan partials
__device__ __align__(16) int    g_bsumx[128];
__device__ __align__(16) float  g_bn[512];                 // [0:128) sum, [128:256) sumsq, [256:384) scale, [384:512) shift
__device__ int g_is64;

// -------------------- dtype detect ------------------------------------------
__global__ void k_detect(const long long* __restrict__ ei) {
    long long stride = NEDGES / 256;
    long long pos = (long long)threadIdx.x * stride;
    long long v = ei[pos];
    bool bad = ((unsigned long long)v >= (unsigned long long)NNODES);
    unsigned anybad = __ballot_sync(0xffffffffu, bad);
    __shared__ int sbad[8];
    int w = threadIdx.x >> 5;
    if ((threadIdx.x & 31) == 0) sbad[w] = (anybad != 0);
    __syncthreads();
    if (threadIdx.x == 0) {
        int any = 0;
        #pragma unroll
        for (int i = 0; i < 8; i++) any |= sbad[i];
        g_is64 = any ? 0 : 1;
    }
}

// -------------------- W fp32 -> fp16 precompute (W1, W2, Wf-padded) ----------
__global__ void k_wconv(const float* __restrict__ W1, const float* __restrict__ W2,
                        const float* __restrict__ Wf) {
    int i = blockIdx.x * 256 + threadIdx.x;   // 64 blocks x 256 = 16384
    g_w1h[i] = __float2half(W1[i]);
    g_w2h[i] = __float2half(W2[i]);
    if (i < DH * 64) {
        int col = i & 63;
        g_wfh[i] = (col < DOUT) ? __float2half(Wf[(i >> 6) * DOUT + col]) : __float2half(0.f);
    }
}

// -------------------- zero helpers ------------------------------------------
__global__ void k_zero(float4* __restrict__ p, int n4) {
    int i = blockIdx.x * blockDim.x + threadIdx.x;
    int stride = gridDim.x * blockDim.x;
    float4 z = make_float4(0.f, 0.f, 0.f, 0.f);
    for (; i < n4; i += stride) p[i] = z;
}
__global__ void k_zerobn() {
    g_bn[threadIdx.x] = 0.f;  // 256 threads: sums+sumsqs
}

// -------------------- degree (2 edges per thread, vector loads) --------------
__global__ void k_degree(const void* __restrict__ ei) {
    int t = blockIdx.x * blockDim.x + threadIdx.x;
    int e = t * 2;
    if (e >= NEDGES) return;
    int d0, d1;
    if (g_is64) {
        longlong2 p = *(const longlong2*)((const long long*)ei + NEDGES + e);
        d0 = (int)p.x; d1 = (int)p.y;
    } else {
        int2 p = *(const int2*)((const int*)ei + NEDGES + e);
        d0 = p.x; d1 = p.y;
    }
    atomicAdd(&g_cnt[d0], 1);
    atomicAdd(&g_cnt[d1], 1);
}

// -------- exclusive scan phase 1 (also computes dinv — gemm1's only dep) -----
__global__ void k_scan1() {
    __shared__ int sh[1024];
    int t = threadIdx.x;
    int i = blockIdx.x * 1024 + t;
    int v = (i < NNODES) ? g_cnt[i] : 0;
    sh[t] = v;
    __syncthreads();
    for (int off = 1; off < 1024; off <<= 1) {
        int x = (t >= off) ? sh[t - off] : 0;
        __syncthreads();
        sh[t] += x;
        __syncthreads();
    }
    if (i < NNODES) {
        g_off[i] = sh[t] - v;   // exclusive
        g_dinv[i] = rsqrtf((float)v + 1.0f);
    }
    if (t == 1023) g_bsum[blockIdx.x] = sh[1023];
}

__global__ void k_scan2(int nblocks) {
    __shared__ int sh[128];
    int t = threadIdx.x;           // 128 threads
    int v = (t < nblocks) ? g_bsum[t] : 0;
    sh[t] = v;
    __syncthreads();
    #pragma unroll
    for (int off = 1; off < 128; off <<= 1) {
        int x = (t >= off) ? sh[t - off] : 0;
        __syncthreads();
        sh[t] += x;
        __syncthreads();
    }
    if (t < nblocks) g_bsumx[t] = sh[t] - v;   // exclusive
    if (t == 127) g_off[NNODES] = sh[127];
}

__global__ void k_scan3() {
    int i = blockIdx.x * blockDim.x + threadIdx.x;
    if (i < NNODES) {
        int o = g_off[i] + g_bsumx[i >> 10];
        g_off[i] = o;
        g_cur[i] = o;
    }
}

// -------------------- scatter edges into CSR (2 edges per thread) ------------
__global__ void k_scatter(const void* __restrict__ ei) {
    int t = blockIdx.x * blockDim.x + threadIdx.x;
    int e = t * 2;
    if (e >= NEDGES) return;
    int s0, d0, s1, d1;
    if (g_is64) {
        const long long* p = (const long long*)ei;
        longlong2 sp = *(const longlong2*)(p + e);
        longlong2 dp = *(const longlong2*)(p + NEDGES + e);
        s0 = (int)sp.x; s1 = (int)sp.y; d0 = (int)dp.x; d1 = (int)dp.y;
    } else {
        const int* p = (const int*)ei;
        int2 sp = *(const int2*)(p + e);
        int2 dp = *(const int2*)(p + NEDGES + e);
        s0 = sp.x; s1 = sp.y; d0 = dp.x; d1 = dp.y;
    }
    g_csr[atomicAdd(&g_cur[d0], 1)] = s0;
    g_csr[atomicAdd(&g_cur[d1], 1)] = s1;
}

// -------------------- fp16 HMMA GEMM  C[M,128] = dinv[row]*(act(A)@W) --------
// Block: 128x128 tile, 8 warps as 4(M) x 2(N); warp 32x64 = 2x4 m16n16k16 tiles.
template <bool A_HALF, bool APPLY_BN>
__global__ void __launch_bounds__(256)
k_gemm128_h(const void* __restrict__ Av, const __half* __restrict__ Wh,
            __half* __restrict__ C, int M) {
    __shared__ __half As[128][40];    // 128 rows x 32 k (pad 8 halves)
    __shared__ __half Bs[32][136];    // 32 k x 128 n   (pad 8)

    const int tid   = threadIdx.x;
    const int warp  = tid >> 5;
    const int lane  = tid & 31;
    const int warpM = warp >> 1;     // 0..3
    const int warpN = warp & 1;      // 0..1
    const int blockRow = blockIdx.x * 128;

    wmma::fragment<wmma::accumulator, 16, 16, 16, float> acc[2][4];
    #pragma unroll
    for (int i = 0; i < 2; i++)
        #pragma unroll
        for (int j = 0; j < 4; j++)
            wmma::fill_fragment(acc[i][j], 0.0f);

    for (int kt = 0; kt < 4; kt++) {
        // ---- A tile: 128 rows x 32 k (half), BN+ReLU fused in fp16
        #pragma unroll
        for (int it = 0; it < 4; it++) {
            int idx = tid + it * 256;            // 0..1023
            int r   = idx >> 3;                  // 0..127
            int c4  = idx & 7;                   // 4-half group
            int grow = blockRow + r;
            uint2 packed;
            if (A_HALF) {
                uint2 raw = *(const uint2*)((const __half*)Av + (size_t)grow * 128 + kt * 32 + c4 * 4);
                if (APPLY_BN) {
                    int c = kt * 32 + c4 * 4;
                    __half2 sc0 = *(const __half2*)&g_bnh[c];
                    __half2 sc1 = *(const __half2*)&g_bnh[c + 2];
                    __half2 sh0 = *(const __half2*)&g_bnh[128 + c];
                    __half2 sh1 = *(const __half2*)&g_bnh[128 + c + 2];
                    __half2 z = __float2half2_rn(0.f);
                    __half2 v0 = __hmax2(__hfma2(*(__half2*)&raw.x, sc0, sh0), z);
                    __half2 v1 = __hmax2(__hfma2(*(__half2*)&raw.y, sc1, sh1), z);
                    packed.x = *(unsigned*)&v0; packed.y = *(unsigned*)&v1;
                } else {
                    packed = raw;
                }
            } else {
                float4 v = make_float4(0.f, 0.f, 0.f, 0.f);
                if (grow < M) v = *(const float4*)((const float*)Av + (size_t)grow * 128 + kt * 32 + c4 * 4);
                __half2 h0 = __floats2half2_rn(v.x, v.y);
                __half2 h1 = __floats2half2_rn(v.z, v.w);
                packed.x = *(unsigned*)&h0; packed.y = *(unsigned*)&h1;
            }
            *(uint2*)&As[r][c4 * 4] = packed;
        }
        // ---- B tile: 32 k x 128 n, raw fp16 copy
        #pragma unroll
        for (int it = 0; it < 4; it++) {
            int idx = tid + it * 256;
            int r   = idx >> 5;                  // 0..31
            int c4  = idx & 31;
            *(uint2*)&Bs[r][c4 * 4] = *(const uint2*)(Wh + (size_t)(kt * 32 + r) * 128 + c4 * 4);
        }
        __syncthreads();

        #pragma unroll
        for (int ks = 0; ks < 2; ks++) {
            wmma::fragment<wmma::matrix_a, 16, 16, 16, __half, wmma::row_major> af[2];
            wmma::fragment<wmma::matrix_b, 16, 16, 16, __half, wmma::row_major> bfr[4];
            #pragma unroll
            for (int i = 0; i < 2; i++)
                wmma::load_matrix_sync(af[i], &As[warpM * 32 + i * 16][ks * 16], 40);
            #pragma unroll
            for (int j = 0; j < 4; j++)
                wmma::load_matrix_sync(bfr[j], &Bs[ks * 16][warpN * 64 + j * 16], 136);
            #pragma unroll
            for (int i = 0; i < 2; i++)
                #pragma unroll
                for (int j = 0; j < 4; j++)
                    wmma::mma_sync(acc[i][j], af[i], bfr[j], acc[i][j]);
        }
        __syncthreads();
    }

    // ---- direct-register epilogue: fp32 acc * dinv[row] -> fp16 C
    const int gid = lane >> 2;     // 0..7
    const int tig = lane & 3;      // 0..3
    #pragma unroll
    for (int i = 0; i < 2; i++) {
        int r0 = blockRow + warpM * 32 + i * 16 + gid;
        int r1 = r0 + 8;
        float d0 = (r0 < M) ? g_dinv[r0] : 0.f;
        float d1 = (r1 < M) ? g_dinv[r1] : 0.f;
        #pragma unroll
        for (int j = 0; j < 4; j++) {
            int c0 = warpN * 64 + j * 16 + tig * 2;
            __half2 p00 = __floats2half2_rn(acc[i][j].x[0] * d0, acc[i][j].x[1] * d0);
            __half2 p10 = __floats2half2_rn(acc[i][j].x[2] * d1, acc[i][j].x[3] * d1);
            __half2 p01 = __floats2half2_rn(acc[i][j].x[4] * d0, acc[i][j].x[5] * d0);
            __half2 p11 = __floats2half2_rn(acc[i][j].x[6] * d1, acc[i][j].x[7] * d1);
            *(__half2*)(C + (size_t)r0 * 128 + c0)     = p00;
            *(__half2*)(C + (size_t)r1 * 128 + c0)     = p10;
            *(__half2*)(C + (size_t)r0 * 128 + c0 + 8) = p01;
            *(__half2*)(C + (size_t)r1 * 128 + c0 + 8) = p11;
        }
    }
}

// ---------- fp16 HMMA GEMM  C[M,40] = dinv[row]*(relu(bn(A))@Wf) -------------
__global__ void __launch_bounds__(256)
k_gemm40_h(const __half* __restrict__ A, const __half* __restrict__ Wh,
           __half* __restrict__ C, int M) {
    __shared__ __half As[128][40];    // 128 rows x 32 k
    __shared__ __half Bs[32][72];     // 32 k x 64 n (pad 8)

    const int tid   = threadIdx.x;
    const int warp  = tid >> 5;
    const int lane  = tid & 31;
    const int warpM = warp >> 1;     // 0..3
    const int warpN = warp & 1;      // 0..1
    const int blockRow = blockIdx.x * 128;

    wmma::fragment<wmma::accumulator, 16, 16, 16, float> acc[2][2];
    #pragma unroll
    for (int i = 0; i < 2; i++)
        #pragma unroll
        for (int j = 0; j < 2; j++)
            wmma::fill_fragment(acc[i][j], 0.0f);

    for (int kt = 0; kt < 4; kt++) {
        #pragma unroll
        for (int it = 0; it < 4; it++) {
            int idx = tid + it * 256;
            int r   = idx >> 3;
            int c4  = idx & 7;
            int grow = blockRow + r;
            uint2 raw = *(const uint2*)(A + (size_t)grow * 128 + kt * 32 + c4 * 4);
            int c = kt * 32 + c4 * 4;
            __half2 sc0 = *(const __half2*)&g_bnh[c];
            __half2 sc1 = *(const __half2*)&g_bnh[c + 2];
            __half2 sh0 = *(const __half2*)&g_bnh[128 + c];
            __half2 sh1 = *(const __half2*)&g_bnh[128 + c + 2];
            __half2 z = __float2half2_rn(0.f);
            __half2 v0 = __hmax2(__hfma2(*(__half2*)&raw.x, sc0, sh0), z);
            __half2 v1 = __hmax2(__hfma2(*(__half2*)&raw.y, sc1, sh1), z);
            uint2 packed; packed.x = *(unsigned*)&v0; packed.y = *(unsigned*)&v1;
            *(uint2*)&As[r][c4 * 4] = packed;
        }
        #pragma unroll
        for (int it = 0; it < 2; it++) {
            int idx = tid + it * 256;            // 0..511
            int r   = idx >> 4;                  // 0..31
            int c4  = idx & 15;                  // 0..15
            *(uint2*)&Bs[r][c4 * 4] = *(const uint2*)(Wh + (size_t)(kt * 32 + r) * 64 + c4 * 4);
        }
        __syncthreads();

        #pragma unroll
        for (int ks = 0; ks < 2; ks++) {
            wmma::fragment<wmma::matrix_a, 16, 16, 16, __half, wmma::row_major> af[2];
            wmma::fragment<wmma::matrix_b, 16, 16, 16, __half, wmma::row_major> bfr[2];
            #pragma unroll
            for (int i = 0; i < 2; i++)
                wmma::load_matrix_sync(af[i], &As[warpM * 32 + i * 16][ks * 16], 40);
            #pragma unroll
            for (int j = 0; j < 2; j++)
                wmma::load_matrix_sync(bfr[j], &Bs[ks * 16][warpN * 32 + j * 16], 72);
            #pragma unroll
            for (int i = 0; i < 2; i++)
                #pragma unroll
                for (int j = 0; j < 2; j++)
                    wmma::mma_sync(acc[i][j], af[i], bfr[j], acc[i][j]);
        }
        __syncthreads();
    }

    const int gid = lane >> 2;
    const int tig = lane & 3;
    #pragma unroll
    for (int i = 0; i < 2; i++) {
        int r0 = blockRow + warpM * 32 + i * 16 + gid;
        int r1 = r0 + 8;
        float d0 = (r0 < M) ? g_dinv[r0] : 0.f;
        float d1 = (r1 < M) ? g_dinv[r1] : 0.f;
        #pragma unroll
        for (int j = 0; j < 2; j++) {
            int c0 = warpN * 32 + j * 16 + tig * 2;
            if (c0 < DOUT) {
                __half2 p00 = __floats2half2_rn(acc[i][j].x[0] * d0, acc[i][j].x[1] * d0);
                __half2 p10 = __floats2half2_rn(acc[i][j].x[2] * d1, acc[i][j].x[3] * d1);
                *(__half2*)(C + (size_t)r0 * 40 + c0) = p00;
                *(__half2*)(C + (size_t)r1 * 40 + c0) = p10;
            }
            if (c0 + 8 < DOUT) {
                __half2 p01 = __floats2half2_rn(acc[i][j].x[4] * d0, acc[i][j].x[5] * d0);
                __half2 p11 = __floats2half2_rn(acc[i][j].x[6] * d1, acc[i][j].x[7] * d1);
                *(__half2*)(C + (size_t)r0 * 40 + c0 + 8) = p01;
                *(__half2*)(C + (size_t)r1 * 40 + c0 + 8) = p11;
            }
        }
    }
}

// -------------------- CSR aggregation D=128 (fp16 in/out, pure sum) ----------
__global__ void __launch_bounds__(256)
k_agg128(const __half* __restrict__ h, __half* __restrict__ out,
         const float* __restrict__ bias) {
    __shared__ float ssum[128];
    __shared__ float ssq[128];
    int tid  = threadIdx.x;
    int warp = tid >> 5, lane = tid & 31;
    if (tid < 128) { ssum[tid] = 0.f; ssq[tid] = 0.f; }
    __syncthreads();

    int r = blockIdx.x * 8 + warp;
    bool ok = (r < NNODES);       // warp-uniform
    if (ok) {
        const int co = lane * 4;
        float4 acc;
        {
            uint2 raw = *(const uint2*)(h + (size_t)r * 128 + co);   // self (dinv-scaled)
            float2 f0 = __half22float2(*(__half2*)&raw.x);
            float2 f1 = __half22float2(*(__half2*)&raw.y);
            acc.x = f0.x; acc.y = f0.y; acc.z = f1.x; acc.w = f1.y;
        }
        int beg = g_off[r], end = g_off[r + 1];
        int base = beg;
        for (; base + 8 <= end; base += 8) {
            int idx = 0;
            if (lane < 8) idx = g_csr[base + lane];
            #pragma unroll
            for (int j = 0; j < 8; j++) {
                int s = __shfl_sync(0xffffffffu, idx, j);
                uint2 raw = *(const uint2*)(h + (size_t)s * 128 + co);
                float2 f0 = __half22float2(*(__half2*)&raw.x);
                float2 f1 = __half22float2(*(__half2*)&raw.y);
                acc.x += f0.x; acc.y += f0.y; acc.z += f1.x; acc.w += f1.y;
            }
        }
        int rem = end - base;
        if (rem > 0) {
            int idx = 0;
            if (lane < rem) idx = g_csr[base + lane];
            for (int j = 0; j < rem; j++) {
                int s = __shfl_sync(0xffffffffu, idx, j);
                uint2 raw = *(const uint2*)(h + (size_t)s * 128 + co);
                float2 f0 = __half22float2(*(__half2*)&raw.x);
                float2 f1 = __half22float2(*(__half2*)&raw.y);
                acc.x += f0.x; acc.y += f0.y; acc.z += f1.x; acc.w += f1.y;
            }
        }
        float dr = g_dinv[r];
        float4 b = *(const float4*)(bias + co);
        float4 v;
        v.x = fmaf(acc.x, dr, b.x);
        v.y = fmaf(acc.y, dr, b.y);
        v.z = fmaf(acc.z, dr, b.z);
        v.w = fmaf(acc.w, dr, b.w);
        __half2 h0 = __floats2half2_rn(v.x, v.y);
        __half2 h1 = __floats2half2_rn(v.z, v.w);
        uint2 packed; packed.x = *(unsigned*)&h0; packed.y = *(unsigned*)&h1;
        *(uint2*)(out + (size_t)r * 128 + co) = packed;
        atomicAdd(&ssum[co + 0], v.x);
        atomicAdd(&ssum[co + 1], v.y);
        atomicAdd(&ssum[co + 2], v.z);
        atomicAdd(&ssum[co + 3], v.w);
        atomicAdd(&ssq[co + 0], v.x * v.x);
        atomicAdd(&ssq[co + 1], v.y * v.y);
        atomicAdd(&ssq[co + 2], v.z * v.z);
        atomicAdd(&ssq[co + 3], v.w * v.w);
    }
    __syncthreads();
    if (tid < 128) {
        atomicAdd(&g_bn[tid], ssum[tid]);
        atomicAdd(&g_bn[128 + tid], ssq[tid]);
    }
}

__global__ void k_bnfin(const float* __restrict__ g, const float* __restrict__ be) {
    int c = threadIdx.x;  // 128 threads
    float inv_n = 1.0f / (float)NNODES;
    float mean = g_bn[c] * inv_n;
    float var  = g_bn[128 + c] * inv_n - mean * mean;
    float sc = g[c] * rsqrtf(var + BNEPS);
    float sh = be[c] - mean * sc;
    g_bn[256 + c] = sc;
    g_bn[384 + c] = sh;
    g_bnh[c]       = __float2half(sc);
    g_bnh[128 + c] = __float2half(sh);
    g_bn[c] = 0.f;           // reset sums for next layer
    g_bn[128 + c] = 0.f;
}

// ------------- CSR aggregation D=40 (fp16 in) + bias + log_softmax -----------
__global__ void __launch_bounds__(256)
k_agg40(const __half* __restrict__ h, float* __restrict__ out,
        const float* __restrict__ bf) {
    int tid  = threadIdx.x;
    int warp = tid >> 5, lane = tid & 31;
    int r = blockIdx.x * 8 + warp;
    if (r >= NNODES) return;     // warp-uniform exit
    bool cok = (lane < 10);

    const int co = lane * 4;
    float4 acc = make_float4(0.f, 0.f, 0.f, 0.f);
    if (cok) {
        uint2 raw = *(const uint2*)(h + (size_t)r * 40 + co);    // self (dinv-scaled)
        float2 f0 = __half22float2(*(__half2*)&raw.x);
        float2 f1 = __half22float2(*(__half2*)&raw.y);
        acc = make_float4(f0.x, f0.y, f1.x, f1.y);
    }
    int beg = g_off[r], end = g_off[r + 1];
    int base = beg;
    for (; base + 8 <= end; base += 8) {
        int idx = 0;
        if (lane < 8) idx = g_csr[base + lane];
        #pragma unroll
        for (int j = 0; j < 8; j++) {
            int s = __shfl_sync(0xffffffffu, idx, j);
            if (cok) {
                uint2 raw = *(const uint2*)(h + (size_t)s * 40 + co);
                float2 f0 = __half22float2(*(__half2*)&raw.x);
                float2 f1 = __half22float2(*(__half2*)&raw.y);
                acc.x += f0.x; acc.y += f0.y; acc.z += f1.x; acc.w += f1.y;
            }
        }
    }
    int rem = end - base;
    if (rem > 0) {
        int idx = 0;
        if (lane < rem) idx = g_csr[base + lane];
        for (int j = 0; j < rem; j++) {
            int s = __shfl_sync(0xffffffffu, idx, j);
            if (cok) {
                uint2 raw = *(const uint2*)(h + (size_t)s * 40 + co);
                float2 f0 = __half22float2(*(__half2*)&raw.x);
                float2 f1 = __half22float2(*(__half2*)&raw.y);
                acc.x += f0.x; acc.y += f0.y; acc.z += f1.x; acc.w += f1.y;
            }
        }
    }
    float dr = g_dinv[r];
    float4 v = make_float4(-1e30f, -1e30f, -1e30f, -1e30f);
    if (cok) {
        float4 b = *(const float4*)(bf + co);
        v.x = fmaf(acc.x, dr, b.x);
        v.y = fmaf(acc.y, dr, b.y);
        v.z = fmaf(acc.z, dr, b.z);
        v.w = fmaf(acc.w, dr, b.w);
    }
    float m = fmaxf(fmaxf(v.x, v.y), fmaxf(v.z, v.w));
    #pragma unroll
    for (int off = 16; off >= 1; off >>= 1)
        m = fmaxf(m, __shfl_xor_sync(0xffffffffu, m, off));
    float s = 0.f;
    if (cok) s = expf(v.x - m) + expf(v.y - m) + expf(v.z - m) + expf(v.w - m);
    #pragma unroll
    for (int off = 16; off >= 1; off >>= 1)
        s += __shfl_xor_sync(0xffffffffu, s, off);
    float l = m + logf(s);
    if (cok) {
        float4 o = make_float4(v.x - l, v.y - l, v.z - l, v.w - l);
        *(float4*)(out + (size_t)r * 40 + co) = o;
    }
}

// ---------------------------------------------------------------------------
extern "C" void kernel_launch(void* const* d_in, const int* in_sizes, int n_in,
                              void* d_out, int out_size) {
    const float* x   = (const float*)d_in[0];
    const void*  ei  = d_in[1];
    const float* W1  = (const float*)d_in[2];
    const float* b1  = (const float*)d_in[3];
    const float* g1  = (const float*)d_in[4];
    const float* be1 = (const float*)d_in[5];
    const float* W2  = (const float*)d_in[6];
    const float* b2  = (const float*)d_in[7];
    const float* g2  = (const float*)d_in[8];
    const float* be2 = (const float*)d_in[9];
    const float* Wf  = (const float*)d_in[10];
    const float* bf  = (const float*)d_in[11];
    float* out = (float*)d_out;

    __half *ph, *pa, *pw1h, *pw2h, *pwfh;
    float *pbn;
    int   *pcnt;
    cudaGetSymbolAddress((void**)&ph, g_h);
    cudaGetSymbolAddress((void**)&pa, g_a);
    cudaGetSymbolAddress((void**)&pw1h, g_w1h);
    cudaGetSymbolAddress((void**)&pw2h, g_w2h);
    cudaGetSymbolAddress((void**)&pwfh, g_wfh);
    cudaGetSymbolAddress((void**)&pbn, g_bn);
    cudaGetSymbolAddress((void**)&pcnt, g_cnt);
    __half* ph40 = ph;   // reuse g_h for the fp16 [NPAD,40] final-layer features

    const int M = NNODES;
    const int gemmBlocks = (M + 127) / 128;          // 782
    const int edge2Blocks = (NEDGES / 2 + 255) / 256;// 3125
    const int nodeBlocks = (NNODES + 7) / 8;         // 12500
    const int scanBlocks = (NNODES + 1023) / 1024;   // 98

    static cudaStream_t s2 = [] {
        cudaStream_t s; cudaStreamCreateWithFlags(&s, cudaStreamNonBlocking); return s;
    }();
    static cudaEvent_t eStart = [] {
        cudaEvent_t e; cudaEventCreateWithFlags(&e, cudaEventDisableTiming); return e;
    }();
    static cudaEvent_t eDinv = [] {
        cudaEvent_t e; cudaEventCreateWithFlags(&e, cudaEventDisableTiming); return e;
    }();
    static cudaEvent_t eGemm1 = [] {
        cudaEvent_t e; cudaEventCreateWithFlags(&e, cudaEventDisableTiming); return e;
    }();

    // ---- stream 0: CSR build chain; s2: wconv + layer-1 GEMM (needs dinv only)
    k_detect<<<1, 256>>>((const long long*)ei);
    k_zero<<<64, 256>>>((float4*)pcnt, NNODES / 4);
    k_zerobn<<<1, 256>>>();
    cudaEventRecord(eStart, 0);
    cudaStreamWaitEvent(s2, eStart, 0);
    k_wconv<<<64, 256, 0, s2>>>(W1, W2, Wf);

    k_degree<<<edge2Blocks, 256>>>(ei);
    k_scan1<<<scanBlocks, 1024>>>();                 // also computes g_dinv
    cudaEventRecord(eDinv, 0);
    cudaStreamWaitEvent(s2, eDinv, 0);
    k_gemm128_h<false, false><<<gemmBlocks, 256, 0, s2>>>(x, pw1h, ph, M);
    cudaEventRecord(eGemm1, s2);

    k_scan2<<<1, 128>>>(scanBlocks);
    k_scan3<<<(NNODES + 255) / 256, 256>>>();
    k_scatter<<<edge2Blocks, 256>>>(ei);
    cudaStreamWaitEvent(0, eGemm1, 0);

    // ---- layer 1 aggregation onward (serial on stream 0) ----
    k_agg128<<<nodeBlocks, 256>>>(ph, pa, b1);
    k_bnfin<<<1, 128>>>(g1, be1);

    // ---- layer 2 ----
    k_gemm128_h<true, true><<<gemmBlocks, 256>>>(pa, pw2h, ph, M);
    k_agg128<<<nodeBlocks, 256>>>(ph, pa, b2);
    k_bnfin<<<1, 128>>>(g2, be2);

    // ---- layer 3 ----
    k_gemm40_h<<<gemmBlocks, 256>>>(pa, pwfh, ph40, M);
    k_agg40<<<nodeBlocks, 256>>>(ph40, out, bf);
}